// round 9
// baseline (speedup 1.0000x reference)
#include <cuda_runtime.h>
#include <cstdint>

#define NB   8
#define CIN  256
#define HW   4096
#define CATT 128
#define COUT 256

// Scratch (device globals; no allocation allowed)
__device__ float g_feat[(size_t)NB * COUT * HW];   // [n][c][pos]
__device__ float g_attT[(size_t)NB * HW * CATT];   // [n][pos][c], tf32-rounded
__device__ float g_energy[(size_t)NB * HW * HW];   // [n][i][j] raw (pre-softmax)
__device__ float g_rmax[(size_t)NB * HW];          // row max
__device__ float g_rden[(size_t)NB * HW];          // row sum of exp(e - max)

// ===========================================================================
// Helpers — family-neutral PTX (sm_80+)
// ===========================================================================
__device__ __forceinline__ uint32_t smem_u32(const void* p) {
    uint32_t a;
    asm("{ .reg .u64 t; cvta.to.shared.u64 t, %1; cvt.u32.u64 %0, t; }" : "=r"(a) : "l"(p));
    return a;
}
__device__ __forceinline__ void mma_tf32(float c[4],
        uint32_t a0, uint32_t a1, uint32_t a2, uint32_t a3,
        uint32_t b0, uint32_t b1) {
    asm volatile("mma.sync.aligned.m16n8k8.row.col.f32.tf32.tf32.f32 "
                 "{%0,%1,%2,%3}, {%4,%5,%6,%7}, {%8,%9}, {%0,%1,%2,%3};"
                 : "+f"(c[0]), "+f"(c[1]), "+f"(c[2]), "+f"(c[3])
                 : "r"(a0), "r"(a1), "r"(a2), "r"(a3), "r"(b0), "r"(b1));
}
__device__ __forceinline__ float f2tf32f(float x) {
    uint32_t r; asm("cvt.rna.tf32.f32 %0, %1;" : "=r"(r) : "f"(x));
    return __uint_as_float(r);
}
__device__ __forceinline__ float ex2f(float x) {
    float r; asm("ex2.approx.f32 %0, %1;" : "=f"(r) : "f"(x)); return r;
}
#define CP16(dst, src) asm volatile("cp.async.ca.shared.global [%0], [%1], 16;" :: "r"(dst), "l"(src))
#define CP_COMMIT()    asm volatile("cp.async.commit_group;" ::: "memory")
#define CP_WAIT1()     asm volatile("cp.async.wait_group 1;" ::: "memory")
#define CP_WAIT0()     asm volatile("cp.async.wait_group 0;" ::: "memory")
#define L2E 1.4426950408889634f

// ===========================================================================
// Kernel 1: fused 1x1 conv + BN + ReLU, both branches.
// Tile 128(o) x 128(p), 256 thr, micro 8x8, 2-stage cp.async (Kt=16).
// grid.y: 0,1 -> feat (o0=y*128); 2 -> att (o0=0, tf32-rounded, transposed).
// ===========================================================================
__global__ __launch_bounds__(256, 2)
void conv_bn_relu_kernel(const float* __restrict__ x,
                         const float* __restrict__ reduc_w,
                         const float* __restrict__ reduc_gamma,
                         const float* __restrict__ reduc_beta,
                         const float* __restrict__ reduc_mean,
                         const float* __restrict__ reduc_var,
                         const float* __restrict__ att_w,
                         const float* __restrict__ att_gamma,
                         const float* __restrict__ att_beta,
                         const float* __restrict__ att_mean,
                         const float* __restrict__ att_var) {
    __shared__ float Ws[2][128][20];   // [o][k] padded
    __shared__ float Xs[2][16][132];   // [k][p] padded

    const int n  = blockIdx.z;
    const int p0 = blockIdx.x * 128;
    const bool isAtt = (blockIdx.y == 2);
    const int o0 = isAtt ? 0 : blockIdx.y * 128;
    const float* w     = isAtt ? att_w     : reduc_w;
    const float* gamma = isAtt ? att_gamma : reduc_gamma;
    const float* beta  = isAtt ? att_beta  : reduc_beta;
    const float* mean  = isAtt ? att_mean  : reduc_mean;
    const float* var   = isAtt ? att_var   : reduc_var;

    const int tid = threadIdx.x;
    const int tx = tid & 15, ty = tid >> 4;
    const float* X = x + (size_t)n * CIN * HW;

    auto load_stage = [&](int s, int k0) {
        #pragma unroll
        for (int i = tid; i < 512; i += 256) {       // W: 128 rows x 16 k
            int m = i >> 2, k4 = i & 3;
            CP16(smem_u32(&Ws[s][m][k4 * 4]), w + (size_t)(o0 + m) * CIN + k0 + k4 * 4);
        }
        #pragma unroll
        for (int i = tid; i < 512; i += 256) {       // X: 16 k x 128 p
            int k = i >> 5, p4 = i & 31;
            CP16(smem_u32(&Xs[s][k][p4 * 4]), X + (size_t)(k0 + k) * HW + p0 + p4 * 4);
        }
        CP_COMMIT();
    };

    float acc[8][8] = {};
    load_stage(0, 0);
    load_stage(1, 16);

    for (int ks = 0; ks < 16; ks++) {
        CP_WAIT1();
        __syncthreads();
        const int s = ks & 1;
        #pragma unroll
        for (int k = 0; k < 16; k++) {
            float a[8];
            #pragma unroll
            for (int i = 0; i < 8; i++) a[i] = Ws[s][ty * 8 + i][k];
            float4 b0 = *(const float4*)&Xs[s][k][tx * 8];
            float4 b1 = *(const float4*)&Xs[s][k][tx * 8 + 4];
            float b[8] = {b0.x, b0.y, b0.z, b0.w, b1.x, b1.y, b1.z, b1.w};
            #pragma unroll
            for (int i = 0; i < 8; i++)
                #pragma unroll
                for (int j = 0; j < 8; j++)
                    acc[i][j] = fmaf(a[i], b[j], acc[i][j]);
        }
        __syncthreads();
        if (ks + 2 < 16) load_stage(s, (ks + 2) * 16);
        else CP_COMMIT();
    }
    CP_WAIT0();

    // BN + ReLU in place
    #pragma unroll
    for (int i = 0; i < 8; i++) {
        int o = o0 + ty * 8 + i;
        float inv  = gamma[o] * rsqrtf(var[o] + 1e-5f);
        float bias = beta[o] - mean[o] * inv;
        #pragma unroll
        for (int j = 0; j < 8; j++)
            acc[i][j] = fmaxf(acc[i][j] * inv + bias, 0.0f);
    }
    if (isAtt) {
        // tf32(rna)-round once; stored transposed [pos][c]
        #pragma unroll
        for (int j = 0; j < 8; j++) {
            int p = p0 + tx * 8 + j;
            float4 q0 = make_float4(f2tf32f(acc[0][j]), f2tf32f(acc[1][j]),
                                    f2tf32f(acc[2][j]), f2tf32f(acc[3][j]));
            float4 q1 = make_float4(f2tf32f(acc[4][j]), f2tf32f(acc[5][j]),
                                    f2tf32f(acc[6][j]), f2tf32f(acc[7][j]));
            float* dst = &g_attT[((size_t)n * HW + p) * CATT + ty * 8];
            *(float4*)dst       = q0;
            *(float4*)(dst + 4) = q1;
        }
    } else {
        #pragma unroll
        for (int i = 0; i < 8; i++) {
            int o = o0 + ty * 8 + i;
            float* dst = &g_feat[((size_t)n * COUT + o) * HW + p0 + tx * 8];
            *(float4*)dst       = make_float4(acc[i][0], acc[i][1], acc[i][2], acc[i][3]);
            *(float4*)(dst + 4) = make_float4(acc[i][4], acc[i][5], acc[i][6], acc[i][7]);
        }
    }
}

// ===========================================================================
// Kernel 2: energy + online softmax stats.
// CTA owns i-stripe [i0,i0+128); loops 32 j-tiles.  A resident; B double-
// buffered; prefetch issued BEFORE epilogue; epilogue writes straight from
// registers (float2, sector-full) and keeps per-thread online (M,D); one
// cross-thread combine at the end.
// ===========================================================================
#define E_LD 132
#define E_SMEM (3 * 128 * E_LD * 4)   // 202752

__global__ __launch_bounds__(256, 1)
void energy_fused_kernel(const float* __restrict__ mask) {
    extern __shared__ float sm[];
    float* As = sm;

    const int tid  = threadIdx.x;
    const int wid  = tid >> 5, lane = tid & 31;
    const int n  = blockIdx.y;
    const int i0 = blockIdx.x * 128;
    const float* attn = g_attT + (size_t)n * HW * CATT;

    #pragma unroll
    for (int idx = tid; idx < 4096; idx += 256) {
        int row = idx >> 5, ch = idx & 31;
        CP16(smem_u32(&As[row * E_LD + ch * 4]),
             attn + (size_t)(i0 + row) * CATT + ch * 4);
    }
    CP_COMMIT();

    auto fill_B = [&](int buf, int jt) {
        float* B = sm + (1 + buf) * 128 * E_LD;
        int jb0 = jt * 128;
        #pragma unroll
        for (int idx = tid; idx < 4096; idx += 256) {
            int row = idx >> 5, ch = idx & 31;
            CP16(smem_u32(&B[row * E_LD + ch * 4]),
                 attn + (size_t)(jb0 + row) * CATT + ch * 4);
        }
        CP_COMMIT();
    };
    fill_B(0, 0);
    fill_B(1, 1);

    const int wm = wid & 1, wn = wid >> 1;
    const int r = lane >> 2, kq = lane & 3;
    const float inv_s = 0.08838834764831845f;  // 1/(1e-8+sqrt(128))

    // 8 row-slots per thread: slot s -> row = wm*64 + (s>>1)*16 + r + (s&1)*8
    float Mreg[8], Dreg[8];
    #pragma unroll
    for (int s = 0; s < 8; s++) { Mreg[s] = -1e30f; Dreg[s] = 0.0f; }

    const float* maskn = mask + (size_t)n * HW;

    for (int t = 0; t < 32; t++) {
        CP_WAIT1();
        __syncthreads();
        float* Bs = sm + (1 + (t & 1)) * 128 * E_LD;

        float cc[4][4][4] = {};
        #pragma unroll 2
        for (int ks = 0; ks < 16; ks++) {
            const int k8 = ks * 8;
            uint32_t af[4][4], bf[4][2];
            #pragma unroll
            for (int mt = 0; mt < 4; mt++) {
                int mb = wm * 64 + mt * 16;
                af[mt][0] = __float_as_uint(As[(mb + r) * E_LD + k8 + kq]);
                af[mt][1] = __float_as_uint(As[(mb + r + 8) * E_LD + k8 + kq]);
                af[mt][2] = __float_as_uint(As[(mb + r) * E_LD + k8 + kq + 4]);
                af[mt][3] = __float_as_uint(As[(mb + r + 8) * E_LD + k8 + kq + 4]);
            }
            #pragma unroll
            for (int nt = 0; nt < 4; nt++) {
                int nb = wn * 32 + nt * 8;
                bf[nt][0] = __float_as_uint(Bs[(nb + r) * E_LD + k8 + kq]);
                bf[nt][1] = __float_as_uint(Bs[(nb + r) * E_LD + k8 + kq + 4]);
            }
            #pragma unroll
            for (int mt = 0; mt < 4; mt++)
                #pragma unroll
                for (int nt = 0; nt < 4; nt++)
                    mma_tf32(cc[mt][nt], af[mt][0], af[mt][1], af[mt][2], af[mt][3],
                             bf[nt][0], bf[nt][1]);
        }
        __syncthreads();                       // Bs reads complete

        // Prefetch next B NOW so the async fill overlaps the epilogue below.
        if (t + 2 < 32) fill_B(t & 1, t + 2);
        else CP_COMMIT();

        // Epilogue: scale + mask -> cc, direct float2 stores (sector-full).
        const int j0 = t * 128;
        #pragma unroll
        for (int nt = 0; nt < 4; nt++) {
            int jb = wn * 32 + nt * 8 + kq * 2;
            float2 mm = *(const float2*)&maskn[j0 + jb];
            float mx = (mm.x - 1.0f) * 1e8f;
            float my = (mm.y - 1.0f) * 1e8f;
            #pragma unroll
            for (int mt = 0; mt < 4; mt++) {
                int ib = wm * 64 + mt * 16 + r;
                float e0 = cc[mt][nt][0] * inv_s + mx;
                float e1 = cc[mt][nt][1] * inv_s + my;
                float e2 = cc[mt][nt][2] * inv_s + mx;
                float e3 = cc[mt][nt][3] * inv_s + my;
                cc[mt][nt][0] = e0; cc[mt][nt][1] = e1;
                cc[mt][nt][2] = e2; cc[mt][nt][3] = e3;
                *(float2*)&g_energy[((size_t)n * HW + i0 + ib) * HW + j0 + jb]
                    = make_float2(e0, e1);
                *(float2*)&g_energy[((size_t)n * HW + i0 + ib + 8) * HW + j0 + jb]
                    = make_float2(e2, e3);
            }
        }
        // Online (M,D) per row-slot over this tile's 8 values.
        #pragma unroll
        for (int s = 0; s < 8; s++) {
            const int mt = s >> 1, h2 = (s & 1) * 2;
            float v0 = cc[mt][0][h2],     v1 = cc[mt][0][h2 + 1];
            float v2 = cc[mt][1][h2],     v3 = cc[mt][1][h2 + 1];
            float v4 = cc[mt][2][h2],     v5 = cc[mt][2][h2 + 1];
            float v6 = cc[mt][3][h2],     v7 = cc[mt][3][h2 + 1];
            float mrow = fmaxf(fmaxf(fmaxf(v0, v1), fmaxf(v2, v3)),
                               fmaxf(fmaxf(v4, v5), fmaxf(v6, v7)));
            float Mn = fmaxf(Mreg[s], mrow);
            float d = ex2f((v0 - Mn) * L2E) + ex2f((v1 - Mn) * L2E)
                    + ex2f((v2 - Mn) * L2E) + ex2f((v3 - Mn) * L2E)
                    + ex2f((v4 - Mn) * L2E) + ex2f((v5 - Mn) * L2E)
                    + ex2f((v6 - Mn) * L2E) + ex2f((v7 - Mn) * L2E);
            Dreg[s] = Dreg[s] * ex2f((Mreg[s] - Mn) * L2E) + d;
            Mreg[s] = Mn;
        }
    }
    CP_WAIT0();
    __syncthreads();                           // As/B regions now reusable

    // Cross-thread combine: 16 partials per row (wn x kq), once.
    float* smM = sm;                // [128][16]
    float* smD = sm + 2048;
    const int pidx = wn * 4 + kq;
    #pragma unroll
    for (int s = 0; s < 8; s++) {
        int row = wm * 64 + (s >> 1) * 16 + r + (s & 1) * 8;
        smM[row * 16 + pidx] = Mreg[s];
        smD[row * 16 + pidx] = Dreg[s];
    }
    __syncthreads();
    if (tid < 128) {
        float M = -1e30f;
        #pragma unroll
        for (int p = 0; p < 16; p++) M = fmaxf(M, smM[tid * 16 + p]);
        float D = 0.0f;
        #pragma unroll
        for (int p = 0; p < 16; p++)
            D += smD[tid * 16 + p] * ex2f((smM[tid * 16 + p] - M) * L2E);
        g_rmax[(size_t)n * HW + i0 + tid] = M;
        g_rden[(size_t)n * HW + i0 + tid] = D;
    }
}

// ===========================================================================
// Kernel 3: out = softmax(E) @ feat^T, fused normalize.
// CTA: M=128(i) x N=256(c), K=4096, Kt=64, 2-stage cp.async.
// A stage transformed in place: w = exp2(e*L2E + bias_row),
// bias_row = -M*L2E - log2(D)  (folds max and 1/denominator).
// ===========================================================================
#define O_LD 68
#define O_ABYTES (128 * O_LD * 4)          // 34816
#define O_STAGE ((128 + 256) * O_LD * 4)   // 104448
#define O_SMEM  (2 * O_STAGE)              // 208896
#define O_NIT   64

__global__ __launch_bounds__(256, 1)
void out_mma_kernel(const float* __restrict__ mask, float* __restrict__ out) {
    extern __shared__ char smc[];
    __shared__ float Eb[128];
    const uint32_t sb = smem_u32(smc);
    const int tid  = threadIdx.x;
    const int wid  = tid >> 5, lane = tid & 31;
    const int n  = blockIdx.y;
    const int i0 = blockIdx.x * 128;
    const float* Wg = g_energy + (size_t)n * HW * HW;     // [i][j] raw
    const float* F  = g_feat   + (size_t)n * COUT * HW;   // [c][j]

    if (tid < 128) {
        float M = g_rmax[(size_t)n * HW + i0 + tid];
        float D = g_rden[(size_t)n * HW + i0 + tid];
        Eb[tid] = fmaf(-M, L2E, -__log2f(D));
    }

    auto load_stage = [&](int s, int kt) {
        uint32_t base = sb + (uint32_t)s * O_STAGE;
        #pragma unroll
        for (int idx = tid; idx < 6144; idx += 256) {
            if (idx < 2048) {                  // A: 128 rows x 64 k
                int row = idx >> 4, ch = idx & 15;
                CP16(base + row * 272 + ch * 16,
                     Wg + (size_t)(i0 + row) * HW + kt + ch * 4);
            } else {                           // B: 256 rows x 64 k
                int q = idx - 2048;
                int row = q >> 4, ch = q & 15;
                CP16(base + O_ABYTES + row * 272 + ch * 16,
                     F + (size_t)row * HW + kt + ch * 4);
            }
        }
        CP_COMMIT();
    };

    load_stage(0, 0);
    load_stage(1, 64);

    const int wm = wid & 1, wn = wid >> 1;
    const int r = lane >> 2, kq = lane & 3;
    float cc[4][8][4] = {};

    for (int it = 0; it < O_NIT; ++it) {
        CP_WAIT1();
        __syncthreads();
        float* Ap = (float*)(smc + (it & 1) * O_STAGE);

        // In-place softmax transform of this stage's A (energy) tile.
        #pragma unroll
        for (int idx = tid; idx < 2048; idx += 256) {
            int row = idx >> 4, ch = idx & 15;
            float4 v = *(const float4*)&Ap[row * O_LD + ch * 4];
            float b = Eb[row];
            v.x = ex2f(fmaf(v.x, L2E, b));
            v.y = ex2f(fmaf(v.y, L2E, b));
            v.z = ex2f(fmaf(v.z, L2E, b));
            v.w = ex2f(fmaf(v.w, L2E, b));
            *(float4*)&Ap[row * O_LD + ch * 4] = v;
        }
        __syncthreads();

        const float* As = Ap;
        const float* Bs = Ap + 128 * O_LD;
        #pragma unroll
        for (int ks = 0; ks < 8; ks++) {
            const int k8 = ks * 8;
            uint32_t af[4][4];
            #pragma unroll
            for (int mt = 0; mt < 4; mt++) {
                int mb = wm * 64 + mt * 16;
                af[mt][0] = __float_as_uint(As[(mb + r) * O_LD + k8 + kq]);
                af[mt][1] = __float_as_uint(As[(mb + r + 8) * O_LD + k8 + kq]);
                af[mt][2] = __float_as_uint(As[(mb + r) * O_LD + k8 + kq + 4]);
                af[mt][3] = __float_as_uint(As[(mb + r + 8) * O_LD + k8 + kq + 4]);
            }
            #pragma unroll
            for (int nt = 0; nt < 8; nt++) {
                int nb = wn * 64 + nt * 8;
                uint32_t b0 = __float_as_uint(Bs[(nb + r) * O_LD + k8 + kq]);
                uint32_t b1 = __float_as_uint(Bs[(nb + r) * O_LD + k8 + kq + 4]);
                #pragma unroll
                for (int mt = 0; mt < 4; mt++)
                    mma_tf32(cc[mt][nt], af[mt][0], af[mt][1], af[mt][2], af[mt][3], b0, b1);
            }
        }
        __syncthreads();
        if (it + 2 < O_NIT) load_stage(it & 1, (it + 2) * 64);
        else CP_COMMIT();
    }
    CP_WAIT0();
    __syncthreads();

    // Stage C: S[c_local][i_local], stride 132; then masked coalesced store.
    float* S = (float*)smc;
    #pragma unroll
    for (int mt = 0; mt < 4; mt++) {
        int ib = wm * 64 + mt * 16 + r;
        #pragma unroll
        for (int nt = 0; nt < 8; nt++) {
            int cb = wn * 64 + nt * 8 + kq * 2;
            S[cb * 132 + ib]           = cc[mt][nt][0];
            S[(cb + 1) * 132 + ib]     = cc[mt][nt][1];
            S[cb * 132 + ib + 8]       = cc[mt][nt][2];
            S[(cb + 1) * 132 + ib + 8] = cc[mt][nt][3];
        }
    }
    __syncthreads();

    #pragma unroll 4
    for (int idx = tid; idx < 8192; idx += 256) {
        int row = idx >> 5, ch = idx & 31;
        int ii = i0 + ch * 4;
        float4 v = *(const float4*)&S[row * 132 + ch * 4];
        float4 mm = *(const float4*)&mask[(size_t)n * HW + ii];
        v.x *= mm.x; v.y *= mm.y; v.z *= mm.z; v.w *= mm.w;
        *(float4*)&out[((size_t)n * COUT + row) * HW + ii] = v;
    }
}

// ===========================================================================
extern "C" void kernel_launch(void* const* d_in, const int* in_sizes, int n_in,
                              void* d_out, int out_size) {
    const float* x           = (const float*)d_in[0];
    const float* mask        = (const float*)d_in[1];
    const float* reduc_w     = (const float*)d_in[2];
    const float* reduc_gamma = (const float*)d_in[3];
    const float* reduc_beta  = (const float*)d_in[4];
    const float* reduc_mean  = (const float*)d_in[5];
    const float* reduc_var   = (const float*)d_in[6];
    const float* att_w       = (const float*)d_in[7];
    const float* att_gamma   = (const float*)d_in[8];
    const float* att_beta    = (const float*)d_in[9];
    const float* att_mean    = (const float*)d_in[10];
    const float* att_var     = (const float*)d_in[11];
    float* out = (float*)d_out;

    cudaFuncSetAttribute(energy_fused_kernel, cudaFuncAttributeMaxDynamicSharedMemorySize, E_SMEM);
    cudaFuncSetAttribute(out_mma_kernel,      cudaFuncAttributeMaxDynamicSharedMemorySize, O_SMEM);

    conv_bn_relu_kernel<<<dim3(HW / 128, 3, NB), 256>>>(
        x, reduc_w, reduc_gamma, reduc_beta, reduc_mean, reduc_var,
        att_w, att_gamma, att_beta, att_mean, att_var);

    energy_fused_kernel<<<dim3(HW / 128, NB), 256, E_SMEM>>>(mask);

    out_mma_kernel<<<dim3(HW / 128, NB), 256, O_SMEM>>>(mask, out);
}

// round 13
// speedup vs baseline: 1.2672x; 1.2672x over previous
#include <cuda_runtime.h>
#include <cstdint>

#define NB   8
#define CIN  256
#define HW   4096
#define CATT 128
#define COUT 256

// Scratch (device globals; no allocation allowed)
__device__ float g_feat[(size_t)NB * COUT * HW];   // [n][c][pos]
__device__ float g_attT[(size_t)NB * HW * CATT];   // [n][pos][c], tf32-rounded
__device__ float g_energy[(size_t)NB * HW * HW];   // [n][i][j]
__device__ float g_xtf [(size_t)NB * CIN * HW];    // x, tf32-rna-rounded
__device__ float g_wtf [(size_t)(COUT + CATT) * CIN]; // [feat W ; att W], rna

// ===========================================================================
// Helpers — family-neutral PTX (sm_80+)
// ===========================================================================
__device__ __forceinline__ uint32_t smem_u32(const void* p) {
    uint32_t a;
    asm("{ .reg .u64 t; cvta.to.shared.u64 t, %1; cvt.u32.u64 %0, t; }" : "=r"(a) : "l"(p));
    return a;
}
__device__ __forceinline__ void mma_tf32(float c[4],
        uint32_t a0, uint32_t a1, uint32_t a2, uint32_t a3,
        uint32_t b0, uint32_t b1) {
    asm volatile("mma.sync.aligned.m16n8k8.row.col.f32.tf32.tf32.f32 "
                 "{%0,%1,%2,%3}, {%4,%5,%6,%7}, {%8,%9}, {%0,%1,%2,%3};"
                 : "+f"(c[0]), "+f"(c[1]), "+f"(c[2]), "+f"(c[3])
                 : "r"(a0), "r"(a1), "r"(a2), "r"(a3), "r"(b0), "r"(b1));
}
__device__ __forceinline__ float f2tf32f(float x) {
    uint32_t r; asm("cvt.rna.tf32.f32 %0, %1;" : "=r"(r) : "f"(x));
    return __uint_as_float(r);
}
#define CP16(dst, src) asm volatile("cp.async.ca.shared.global [%0], [%1], 16;" :: "r"(dst), "l"(src))
#define CP_COMMIT()    asm volatile("cp.async.commit_group;" ::: "memory")
#define CP_WAIT1()     asm volatile("cp.async.wait_group 1;" ::: "memory")
#define CP_WAIT0()     asm volatile("cp.async.wait_group 0;" ::: "memory")

// ===========================================================================
// Kernel 0: prep — tf32(rna)-round X and both weight matrices into scratch.
// ===========================================================================
__global__ __launch_bounds__(256)
void prep_kernel(const float* __restrict__ x,
                 const float* __restrict__ reduc_w,
                 const float* __restrict__ att_w) {
    const size_t i = ((size_t)blockIdx.x * 256 + threadIdx.x) * 4;
    if (i < (size_t)NB * CIN * HW) {
        float4 v = *(const float4*)(x + i);
        v.x = f2tf32f(v.x); v.y = f2tf32f(v.y);
        v.z = f2tf32f(v.z); v.w = f2tf32f(v.w);
        *(float4*)(g_xtf + i) = v;
    }
    if (blockIdx.x < 96) {
        const size_t j = ((size_t)blockIdx.x * 256 + threadIdx.x) * 4;
        const size_t featN = (size_t)COUT * CIN;
        float4 v = (j < featN) ? *(const float4*)(reduc_w + j)
                               : *(const float4*)(att_w + (j - featN));
        v.x = f2tf32f(v.x); v.y = f2tf32f(v.y);
        v.z = f2tf32f(v.z); v.w = f2tf32f(v.w);
        *(float4*)(g_wtf + j) = v;
    }
}

// ===========================================================================
// Kernel 1: conv+BN+ReLU via tf32 MMA.
// Y[o,p] = sum_c W[o,c] * X[c,p].  CTA: M=128(o) x N=256(p), K=256, Kt=32,
// 3-stage cp.async.  8 warps 2(M)x4(N), warp tile 64x64.
// grid.y: 0,1 feat; 2 att (transposed out, re-rounded).
// ===========================================================================
#define C_ALD 36
#define C_BLD 264
#define C_ABYTES (128 * C_ALD * 4)            // 18432
#define C_STAGE  (C_ABYTES + 32 * C_BLD * 4)  // 52224
#define C_SMEM   (3 * C_STAGE)                // 156672

__global__ __launch_bounds__(256, 1)
void conv_mma_kernel(const float* __restrict__ reduc_gamma,
                     const float* __restrict__ reduc_beta,
                     const float* __restrict__ reduc_mean,
                     const float* __restrict__ reduc_var,
                     const float* __restrict__ att_gamma,
                     const float* __restrict__ att_beta,
                     const float* __restrict__ att_mean,
                     const float* __restrict__ att_var) {
    extern __shared__ char smc[];
    __shared__ float invS[128], biasS[128];
    const uint32_t sb = smem_u32(smc);
    const int tid = threadIdx.x;
    const int wid = tid >> 5, lane = tid & 31;
    const int n  = blockIdx.z;
    const int p0 = blockIdx.x * 256;
    const int br = blockIdx.y;
    const bool isAtt = (br == 2);
    const float* W = g_wtf + (isAtt ? (size_t)COUT * CIN : (size_t)br * 128 * CIN);
    const float* X = g_xtf + (size_t)n * CIN * HW;

    if (tid < 128) {
        int og = isAtt ? tid : br * 128 + tid;
        float g = isAtt ? att_gamma[og] : reduc_gamma[og];
        float v = isAtt ? att_var[og]   : reduc_var[og];
        float b = isAtt ? att_beta[og]  : reduc_beta[og];
        float m = isAtt ? att_mean[og]  : reduc_mean[og];
        float inv = g * rsqrtf(v + 1e-5f);
        invS[tid]  = inv;
        biasS[tid] = b - m * inv;
    }

    auto load_stage = [&](int s, int kt) {
        uint32_t base = sb + (uint32_t)s * C_STAGE;
        #pragma unroll
        for (int idx = tid; idx < 1024; idx += 256) {      // A: 128 o-rows x 32 k
            int row = idx >> 3, ch = idx & 7;
            CP16(base + row * 144 + ch * 16, W + (size_t)row * CIN + kt + ch * 4);
        }
        #pragma unroll
        for (int idx = tid; idx < 2048; idx += 256) {      // B: 32 k-rows x 256 p (64 CP16/row)
            int row = idx >> 6, ch = idx & 63;
            CP16(base + C_ABYTES + row * 1056 + ch * 16,
                 X + (size_t)(kt + row) * HW + p0 + ch * 4);
        }
        CP_COMMIT();
    };

    load_stage(0, 0);
    load_stage(1, 32);

    const int wm = wid & 1, wn = wid >> 1;
    const int r = lane >> 2, kq = lane & 3;
    float cc[4][8][4] = {};

    for (int it = 0; it < 8; ++it) {                       // K=256 / 32
        CP_WAIT1();
        __syncthreads();
        const float* As = (const float*)(smc + (it % 3) * C_STAGE);
        const float* Bs = (const float*)(smc + (it % 3) * C_STAGE + C_ABYTES);
        #pragma unroll
        for (int ks = 0; ks < 4; ks++) {
            const int k8 = ks * 8;
            uint32_t af[4][4];
            #pragma unroll
            for (int mt = 0; mt < 4; mt++) {
                int mb = wm * 64 + mt * 16;
                af[mt][0] = __float_as_uint(As[(mb + r) * C_ALD + k8 + kq]);
                af[mt][1] = __float_as_uint(As[(mb + r + 8) * C_ALD + k8 + kq]);
                af[mt][2] = __float_as_uint(As[(mb + r) * C_ALD + k8 + kq + 4]);
                af[mt][3] = __float_as_uint(As[(mb + r + 8) * C_ALD + k8 + kq + 4]);
            }
            #pragma unroll
            for (int nt = 0; nt < 8; nt++) {
                int nb = wn * 64 + nt * 8;
                uint32_t b0 = __float_as_uint(Bs[(k8 + kq) * C_BLD + nb + r]);
                uint32_t b1 = __float_as_uint(Bs[(k8 + kq + 4) * C_BLD + nb + r]);
                #pragma unroll
                for (int mt = 0; mt < 4; mt++)
                    mma_tf32(cc[mt][nt], af[mt][0], af[mt][1], af[mt][2], af[mt][3], b0, b1);
            }
        }
        __syncthreads();
        if (it + 2 < 8) load_stage((it + 2) % 3, (it + 2) * 32);
        else CP_COMMIT();
    }
    CP_WAIT0();
    __syncthreads();

    // BN + ReLU in registers
    #pragma unroll
    for (int mt = 0; mt < 4; mt++) {
        int ob = wm * 64 + mt * 16 + r;
        float i0 = invS[ob],     b0 = biasS[ob];
        float i1 = invS[ob + 8], b1 = biasS[ob + 8];
        #pragma unroll
        for (int nt = 0; nt < 8; nt++) {
            cc[mt][nt][0] = fmaxf(fmaf(cc[mt][nt][0], i0, b0), 0.0f);
            cc[mt][nt][1] = fmaxf(fmaf(cc[mt][nt][1], i0, b0), 0.0f);
            cc[mt][nt][2] = fmaxf(fmaf(cc[mt][nt][2], i1, b1), 0.0f);
            cc[mt][nt][3] = fmaxf(fmaf(cc[mt][nt][3], i1, b1), 0.0f);
        }
    }

    float* S = (float*)smc;
    if (!isAtt) {
        // Stage S[o][p] (pad 260), coalesced store over p.
        #pragma unroll
        for (int mt = 0; mt < 4; mt++) {
            int ob = wm * 64 + mt * 16 + r;
            #pragma unroll
            for (int nt = 0; nt < 8; nt++) {
                int pb = wn * 64 + nt * 8 + kq * 2;
                S[ob * 260 + pb]           = cc[mt][nt][0];
                S[ob * 260 + pb + 1]       = cc[mt][nt][1];
                S[(ob + 8) * 260 + pb]     = cc[mt][nt][2];
                S[(ob + 8) * 260 + pb + 1] = cc[mt][nt][3];
            }
        }
        __syncthreads();
        #pragma unroll 4
        for (int idx = tid; idx < 8192; idx += 256) {
            int row = idx >> 6, ch = idx & 63;
            float4 v = *(const float4*)&S[row * 260 + ch * 4];
            *(float4*)&g_feat[((size_t)n * COUT + br * 128 + row) * HW + p0 + ch * 4] = v;
        }
    } else {
        // Stage transposed S[p][o] (pad 132), coalesced store over c.
        #pragma unroll
        for (int mt = 0; mt < 4; mt++) {
            int ob = wm * 64 + mt * 16 + r;
            #pragma unroll
            for (int nt = 0; nt < 8; nt++) {
                int pb = wn * 64 + nt * 8 + kq * 2;
                S[pb * 132 + ob]           = cc[mt][nt][0];
                S[(pb + 1) * 132 + ob]     = cc[mt][nt][1];
                S[pb * 132 + ob + 8]       = cc[mt][nt][2];
                S[(pb + 1) * 132 + ob + 8] = cc[mt][nt][3];
            }
        }
        __syncthreads();
        #pragma unroll 4
        for (int idx = tid; idx < 8192; idx += 256) {
            int row = idx >> 5, ch = idx & 31;     // 256 p-rows x 32 float4
            float4 v = *(const float4*)&S[row * 132 + ch * 4];
            v.x = f2tf32f(v.x); v.y = f2tf32f(v.y);
            v.z = f2tf32f(v.z); v.w = f2tf32f(v.w);
            *(float4*)&g_attT[((size_t)n * HW + p0 + row) * CATT + ch * 4] = v;
        }
    }
}

// ===========================================================================
// Kernel 2 (R6, verbatim): energy via mma.sync tf32.
// CTA: 128(i) x 256(j), K=128. 8 warps 2x4, warp tile 64x64.
// ===========================================================================
#define E_LD 132
#define E_SLD 260
#define E_SMEM ((128 + 256) * E_LD * 4)

__global__ __launch_bounds__(256, 1)
void energy_mma_kernel(const float* __restrict__ mask) {
    extern __shared__ float sm[];
    float* As = sm;
    float* Bs = sm + 128 * E_LD;

    const int tid  = threadIdx.x;
    const int wid  = tid >> 5, lane = tid & 31;
    const int n  = blockIdx.z;
    const int i0 = blockIdx.y * 128;
    const int j0 = blockIdx.x * 256;
    const float* attn = g_attT + (size_t)n * HW * CATT;

    #pragma unroll 4
    for (int idx = tid; idx < 4096; idx += 256) {
        int row = idx >> 5, ch = idx & 31;
        *(float4*)&As[row * E_LD + ch * 4] =
            *(const float4*)(attn + (size_t)(i0 + row) * CATT + ch * 4);
    }
    #pragma unroll 4
    for (int idx = tid; idx < 8192; idx += 256) {
        int row = idx >> 5, ch = idx & 31;
        *(float4*)&Bs[row * E_LD + ch * 4] =
            *(const float4*)(attn + (size_t)(j0 + row) * CATT + ch * 4);
    }
    __syncthreads();

    const int wm = wid & 1, wn = wid >> 1;
    const int r = lane >> 2, kq = lane & 3;
    float cc[4][8][4] = {};

    #pragma unroll 2
    for (int ks = 0; ks < 16; ks++) {
        const int k8 = ks * 8;
        uint32_t af[4][4];
        #pragma unroll
        for (int mt = 0; mt < 4; mt++) {
            int mb = wm * 64 + mt * 16;
            af[mt][0] = __float_as_uint(As[(mb + r) * E_LD + k8 + kq]);
            af[mt][1] = __float_as_uint(As[(mb + r + 8) * E_LD + k8 + kq]);
            af[mt][2] = __float_as_uint(As[(mb + r) * E_LD + k8 + kq + 4]);
            af[mt][3] = __float_as_uint(As[(mb + r + 8) * E_LD + k8 + kq + 4]);
        }
        #pragma unroll
        for (int nt = 0; nt < 8; nt++) {
            int nb = wn * 64 + nt * 8;
            uint32_t b0 = __float_as_uint(Bs[(nb + r) * E_LD + k8 + kq]);
            uint32_t b1 = __float_as_uint(Bs[(nb + r) * E_LD + k8 + kq + 4]);
            #pragma unroll
            for (int mt = 0; mt < 4; mt++)
                mma_tf32(cc[mt][nt], af[mt][0], af[mt][1], af[mt][2], af[mt][3], b0, b1);
        }
    }
    __syncthreads();

    float* S = sm;
    #pragma unroll
    for (int mt = 0; mt < 4; mt++) {
        int ib = wm * 64 + mt * 16 + r;
        #pragma unroll
        for (int nt = 0; nt < 8; nt++) {
            int jb = wn * 64 + nt * 8 + kq * 2;
            S[ib * E_SLD + jb]           = cc[mt][nt][0];
            S[ib * E_SLD + jb + 1]       = cc[mt][nt][1];
            S[(ib + 8) * E_SLD + jb]     = cc[mt][nt][2];
            S[(ib + 8) * E_SLD + jb + 1] = cc[mt][nt][3];
        }
    }
    __syncthreads();

    const float inv_s = 0.08838834764831845f;   // 1/(1e-8+sqrt(128))
    #pragma unroll 4
    for (int idx = tid; idx < 8192; idx += 256) {
        int row = idx >> 6, ch = idx & 63;
        int j = j0 + ch * 4;
        float4 v = *(const float4*)&S[row * E_SLD + ch * 4];
        float4 mm = *(const float4*)&mask[(size_t)n * HW + j];
        v.x = v.x * inv_s + (mm.x - 1.0f) * 1e8f;
        v.y = v.y * inv_s + (mm.y - 1.0f) * 1e8f;
        v.z = v.z * inv_s + (mm.z - 1.0f) * 1e8f;
        v.w = v.w * inv_s + (mm.w - 1.0f) * 1e8f;
        *(float4*)&g_energy[((size_t)n * HW + i0 + row) * HW + j] = v;
    }
}

// ===========================================================================
// Kernel 3 (R6, verbatim): row softmax — at DRAM roof.
// ===========================================================================
__global__ void softmax_kernel() {
    const size_t row = blockIdx.x;
    float* E = g_energy + row * HW;
    const int tid = threadIdx.x;

    float v[16];
    float m = -1e30f;
    #pragma unroll
    for (int t = 0; t < 16; t++) {
        v[t] = E[t * 256 + tid];
        m = fmaxf(m, v[t]);
    }
    __shared__ float sred[8];
    #pragma unroll
    for (int o = 16; o > 0; o >>= 1)
        m = fmaxf(m, __shfl_xor_sync(0xffffffffu, m, o));
    if ((tid & 31) == 0) sred[tid >> 5] = m;
    __syncthreads();
    float mAll = sred[0];
    #pragma unroll
    for (int w = 1; w < 8; w++) mAll = fmaxf(mAll, sred[w]);

    float s = 0.0f;
    #pragma unroll
    for (int t = 0; t < 16; t++) { v[t] = __expf(v[t] - mAll); s += v[t]; }
    #pragma unroll
    for (int o = 16; o > 0; o >>= 1)
        s += __shfl_xor_sync(0xffffffffu, s, o);
    __syncthreads();
    if ((tid & 31) == 0) sred[tid >> 5] = s;
    __syncthreads();
    float sAll = 0.0f;
    #pragma unroll
    for (int w = 0; w < 8; w++) sAll += sred[w];

    const float r = 1.0f / sAll;
    #pragma unroll
    for (int t = 0; t < 16; t++) E[t * 256 + tid] = v[t] * r;
}

// ===========================================================================
// Kernel 4 (R6, verbatim): out via mma.sync tf32 + cp.async 3-stage.
// CTA: M=128(i) x N=256(c), K=4096, Kt=32.
// ===========================================================================
#define O_LD 36
#define O_STAGE ((128 + 256) * O_LD * 4)
#define O_SMEM  (3 * O_STAGE)
#define O_NIT   128

__global__ __launch_bounds__(256, 1)
void out_mma_kernel(const float* __restrict__ mask, float* __restrict__ out) {
    extern __shared__ char smc[];
    const uint32_t sb = smem_u32(smc);
    const int tid  = threadIdx.x;
    const int wid  = tid >> 5, lane = tid & 31;
    const int n  = blockIdx.y;
    const int i0 = blockIdx.x * 128;
    const float* Wg = g_energy + (size_t)n * HW * HW;
    const float* F  = g_feat   + (size_t)n * COUT * HW;

    auto load_stage = [&](int s, int kt) {
        uint32_t base = sb + (uint32_t)s * O_STAGE;
        #pragma unroll
        for (int idx = tid; idx < 3072; idx += 256) {
            if (idx < 1024) {
                int row = idx >> 3, ch = idx & 7;
                CP16(base + row * 144 + ch * 16,
                     Wg + (size_t)(i0 + row) * HW + kt + ch * 4);
            } else {
                int q = idx - 1024;
                int row = q >> 3, ch = q & 7;
                CP16(base + 18432 + row * 144 + ch * 16,
                     F + (size_t)row * HW + kt + ch * 4);
            }
        }
        CP_COMMIT();
    };

    load_stage(0, 0);
    load_stage(1, 32);

    const int wm = wid & 1, wn = wid >> 1;
    const int r = lane >> 2, kq = lane & 3;
    float cc[4][8][4] = {};

    for (int it = 0; it < O_NIT; ++it) {
        CP_WAIT1();
        __syncthreads();
        const float* As = (const float*)(smc + (it % 3) * O_STAGE);
        const float* Bs = As + 128 * O_LD;
        #pragma unroll
        for (int ks = 0; ks < 4; ks++) {
            const int k8 = ks * 8;
            uint32_t af[4][4];
            #pragma unroll
            for (int mt = 0; mt < 4; mt++) {
                int mb = wm * 64 + mt * 16;
                af[mt][0] = __float_as_uint(As[(mb + r) * O_LD + k8 + kq]);
                af[mt][1] = __float_as_uint(As[(mb + r + 8) * O_LD + k8 + kq]);
                af[mt][2] = __float_as_uint(As[(mb + r) * O_LD + k8 + kq + 4]);
                af[mt][3] = __float_as_uint(As[(mb + r + 8) * O_LD + k8 + kq + 4]);
            }
            #pragma unroll
            for (int nt = 0; nt < 8; nt++) {
                int nb = wn * 64 + nt * 8;
                uint32_t b0 = __float_as_uint(Bs[(nb + r) * O_LD + k8 + kq]);
                uint32_t b1 = __float_as_uint(Bs[(nb + r) * O_LD + k8 + kq + 4]);
                #pragma unroll
                for (int mt = 0; mt < 4; mt++)
                    mma_tf32(cc[mt][nt], af[mt][0], af[mt][1], af[mt][2], af[mt][3], b0, b1);
            }
        }
        __syncthreads();
        if (it + 2 < O_NIT) load_stage((it + 2) % 3, (it + 2) * 32);
        else CP_COMMIT();
    }
    CP_WAIT0();
    __syncthreads();

    float* S = (float*)smc;
    #pragma unroll
    for (int mt = 0; mt < 4; mt++) {
        int ib = wm * 64 + mt * 16 + r;
        #pragma unroll
        for (int nt = 0; nt < 8; nt++) {
            int cb = wn * 64 + nt * 8 + kq * 2;
            S[cb * 132 + ib]           = cc[mt][nt][0];
            S[(cb + 1) * 132 + ib]     = cc[mt][nt][1];
            S[cb * 132 + ib + 8]       = cc[mt][nt][2];
            S[(cb + 1) * 132 + ib + 8] = cc[mt][nt][3];
        }
    }
    __syncthreads();

    #pragma unroll 4
    for (int idx = tid; idx < 8192; idx += 256) {
        int row = idx >> 5, ch = idx & 31;
        int ii = i0 + ch * 4;
        float4 v = *(const float4*)&S[row * 132 + ch * 4];
        float4 mm = *(const float4*)&mask[(size_t)n * HW + ii];
        v.x *= mm.x; v.y *= mm.y; v.z *= mm.z; v.w *= mm.w;
        *(float4*)&out[((size_t)n * COUT + row) * HW + ii] = v;
    }
}

// ===========================================================================
extern "C" void kernel_launch(void* const* d_in, const int* in_sizes, int n_in,
                              void* d_out, int out_size) {
    const float* x           = (const float*)d_in[0];
    const float* mask        = (const float*)d_in[1];
    const float* reduc_w     = (const float*)d_in[2];
    const float* reduc_gamma = (const float*)d_in[3];
    const float* reduc_beta  = (const float*)d_in[4];
    const float* reduc_mean  = (const float*)d_in[5];
    const float* reduc_var   = (const float*)d_in[6];
    const float* att_w       = (const float*)d_in[7];
    const float* att_gamma   = (const float*)d_in[8];
    const float* att_beta    = (const float*)d_in[9];
    const float* att_mean    = (const float*)d_in[10];
    const float* att_var     = (const float*)d_in[11];
    float* out = (float*)d_out;

    cudaFuncSetAttribute(conv_mma_kernel,   cudaFuncAttributeMaxDynamicSharedMemorySize, C_SMEM);
    cudaFuncSetAttribute(energy_mma_kernel, cudaFuncAttributeMaxDynamicSharedMemorySize, E_SMEM);
    cudaFuncSetAttribute(out_mma_kernel,    cudaFuncAttributeMaxDynamicSharedMemorySize, O_SMEM);

    prep_kernel<<<8192, 256>>>(x, reduc_w, att_w);

    conv_mma_kernel<<<dim3(HW / 256, 3, NB), 256, C_SMEM>>>(
        reduc_gamma, reduc_beta, reduc_mean, reduc_var,
        att_gamma, att_beta, att_mean, att_var);

    energy_mma_kernel<<<dim3(HW / 256, HW / 128, NB), 256, E_SMEM>>>(mask);

    softmax_kernel<<<NB * HW, 256>>>();

    out_mma_kernel<<<dim3(HW / 128, NB), 256, O_SMEM>>>(mask, out);
}

// round 14
// speedup vs baseline: 2.0043x; 1.5817x over previous
#include <cuda_runtime.h>
#include <cuda_fp16.h>
#include <cstdint>

#define NB   8
#define CIN  256
#define HW   4096
#define CATT 128
#define COUT 256

// Scratch (device globals; no allocation allowed)
__device__ __half g_feat_h[(size_t)NB * COUT * HW];  // [n][c][pos] fp16
__device__ __half g_attT_h[(size_t)NB * HW * CATT];  // [n][pos][c] fp16
__device__ float  g_energy[(size_t)NB * HW * HW];    // [n][i][j] f32
__device__ __half g_prob [(size_t)NB * HW * HW];     // softmax(E) fp16
__device__ float  g_xtf  [(size_t)NB * CIN * HW];    // x, tf32-rna
__device__ float  g_wtf  [(size_t)(COUT + CATT) * CIN];

// ===========================================================================
// Helpers — family-neutral PTX (sm_80+)
// ===========================================================================
__device__ __forceinline__ uint32_t smem_u32(const void* p) {
    uint32_t a;
    asm("{ .reg .u64 t; cvta.to.shared.u64 t, %1; cvt.u32.u64 %0, t; }" : "=r"(a) : "l"(p));
    return a;
}
__device__ __forceinline__ void mma_tf32(float c[4],
        uint32_t a0, uint32_t a1, uint32_t a2, uint32_t a3,
        uint32_t b0, uint32_t b1) {
    asm volatile("mma.sync.aligned.m16n8k8.row.col.f32.tf32.tf32.f32 "
                 "{%0,%1,%2,%3}, {%4,%5,%6,%7}, {%8,%9}, {%0,%1,%2,%3};"
                 : "+f"(c[0]), "+f"(c[1]), "+f"(c[2]), "+f"(c[3])
                 : "r"(a0), "r"(a1), "r"(a2), "r"(a3), "r"(b0), "r"(b1));
}
__device__ __forceinline__ void mma_f16(float c[4],
        uint32_t a0, uint32_t a1, uint32_t a2, uint32_t a3,
        uint32_t b0, uint32_t b1) {
    asm volatile("mma.sync.aligned.m16n8k16.row.col.f32.f16.f16.f32 "
                 "{%0,%1,%2,%3}, {%4,%5,%6,%7}, {%8,%9}, {%0,%1,%2,%3};"
                 : "+f"(c[0]), "+f"(c[1]), "+f"(c[2]), "+f"(c[3])
                 : "r"(a0), "r"(a1), "r"(a2), "r"(a3), "r"(b0), "r"(b1));
}
__device__ __forceinline__ float f2tf32f(float x) {
    uint32_t r; asm("cvt.rna.tf32.f32 %0, %1;" : "=r"(r) : "f"(x));
    return __uint_as_float(r);
}
#define CP16(dst, src) asm volatile("cp.async.ca.shared.global [%0], [%1], 16;" :: "r"(dst), "l"(src))
#define CP_COMMIT()    asm volatile("cp.async.commit_group;" ::: "memory")
#define CP_WAIT1()     asm volatile("cp.async.wait_group 1;" ::: "memory")
#define CP_WAIT0()     asm volatile("cp.async.wait_group 0;" ::: "memory")

// ===========================================================================
// Kernel 0: prep — tf32(rna)-round X and both weight matrices.
// ===========================================================================
__global__ __launch_bounds__(256)
void prep_kernel(const float* __restrict__ x,
                 const float* __restrict__ reduc_w,
                 const float* __restrict__ att_w) {
    const size_t i = ((size_t)blockIdx.x * 256 + threadIdx.x) * 4;
    if (i < (size_t)NB * CIN * HW) {
        float4 v = *(const float4*)(x + i);
        v.x = f2tf32f(v.x); v.y = f2tf32f(v.y);
        v.z = f2tf32f(v.z); v.w = f2tf32f(v.w);
        *(float4*)(g_xtf + i) = v;
    }
    if (blockIdx.x < 96) {
        const size_t j = ((size_t)blockIdx.x * 256 + threadIdx.x) * 4;
        const size_t featN = (size_t)COUT * CIN;
        float4 v = (j < featN) ? *(const float4*)(reduc_w + j)
                               : *(const float4*)(att_w + (j - featN));
        v.x = f2tf32f(v.x); v.y = f2tf32f(v.y);
        v.z = f2tf32f(v.z); v.w = f2tf32f(v.w);
        *(float4*)(g_wtf + j) = v;
    }
}

// ===========================================================================
// Kernel 1: conv+BN+ReLU via tf32 MMA; outputs stored fp16.
// CTA: M=128(o) x N=256(p), K=256, Kt=32, 3-stage cp.async.
// grid.y: 0,1 feat; 2 att (transposed [pos][c]).
// ===========================================================================
#define C_ALD 36
#define C_BLD 264
#define C_ABYTES (128 * C_ALD * 4)
#define C_STAGE  (C_ABYTES + 32 * C_BLD * 4)  // 52224
#define C_SMEM   (3 * C_STAGE)                // 156672

__global__ __launch_bounds__(256, 1)
void conv_mma_kernel(const float* __restrict__ reduc_gamma,
                     const float* __restrict__ reduc_beta,
                     const float* __restrict__ reduc_mean,
                     const float* __restrict__ reduc_var,
                     const float* __restrict__ att_gamma,
                     const float* __restrict__ att_beta,
                     const float* __restrict__ att_mean,
                     const float* __restrict__ att_var) {
    extern __shared__ char smc[];
    __shared__ float invS[128], biasS[128];
    const uint32_t sb = smem_u32(smc);
    const int tid = threadIdx.x;
    const int wid = tid >> 5, lane = tid & 31;
    const int n  = blockIdx.z;
    const int p0 = blockIdx.x * 256;
    const int br = blockIdx.y;
    const bool isAtt = (br == 2);
    const float* W = g_wtf + (isAtt ? (size_t)COUT * CIN : (size_t)br * 128 * CIN);
    const float* X = g_xtf + (size_t)n * CIN * HW;

    if (tid < 128) {
        int og = isAtt ? tid : br * 128 + tid;
        float g = isAtt ? att_gamma[og] : reduc_gamma[og];
        float v = isAtt ? att_var[og]   : reduc_var[og];
        float b = isAtt ? att_beta[og]  : reduc_beta[og];
        float m = isAtt ? att_mean[og]  : reduc_mean[og];
        float inv = g * rsqrtf(v + 1e-5f);
        invS[tid]  = inv;
        biasS[tid] = b - m * inv;
    }

    auto load_stage = [&](int s, int kt) {
        uint32_t base = sb + (uint32_t)s * C_STAGE;
        #pragma unroll
        for (int idx = tid; idx < 1024; idx += 256) {
            int row = idx >> 3, ch = idx & 7;
            CP16(base + row * 144 + ch * 16, W + (size_t)row * CIN + kt + ch * 4);
        }
        #pragma unroll
        for (int idx = tid; idx < 2048; idx += 256) {
            int row = idx >> 6, ch = idx & 63;
            CP16(base + C_ABYTES + row * 1056 + ch * 16,
                 X + (size_t)(kt + row) * HW + p0 + ch * 4);
        }
        CP_COMMIT();
    };

    load_stage(0, 0);
    load_stage(1, 32);

    const int wm = wid & 1, wn = wid >> 1;
    const int r = lane >> 2, kq = lane & 3;
    float cc[4][8][4] = {};

    for (int it = 0; it < 8; ++it) {
        CP_WAIT1();
        __syncthreads();
        const float* As = (const float*)(smc + (it % 3) * C_STAGE);
        const float* Bs = (const float*)(smc + (it % 3) * C_STAGE + C_ABYTES);
        #pragma unroll
        for (int ks = 0; ks < 4; ks++) {
            const int k8 = ks * 8;
            uint32_t af[4][4];
            #pragma unroll
            for (int mt = 0; mt < 4; mt++) {
                int mb = wm * 64 + mt * 16;
                af[mt][0] = __float_as_uint(As[(mb + r) * C_ALD + k8 + kq]);
                af[mt][1] = __float_as_uint(As[(mb + r + 8) * C_ALD + k8 + kq]);
                af[mt][2] = __float_as_uint(As[(mb + r) * C_ALD + k8 + kq + 4]);
                af[mt][3] = __float_as_uint(As[(mb + r + 8) * C_ALD + k8 + kq + 4]);
            }
            #pragma unroll
            for (int nt = 0; nt < 8; nt++) {
                int nb = wn * 64 + nt * 8;
                uint32_t b0 = __float_as_uint(Bs[(k8 + kq) * C_BLD + nb + r]);
                uint32_t b1 = __float_as_uint(Bs[(k8 + kq + 4) * C_BLD + nb + r]);
                #pragma unroll
                for (int mt = 0; mt < 4; mt++)
                    mma_tf32(cc[mt][nt], af[mt][0], af[mt][1], af[mt][2], af[mt][3], b0, b1);
            }
        }
        __syncthreads();
        if (it + 2 < 8) load_stage((it + 2) % 3, (it + 2) * 32);
        else CP_COMMIT();
    }
    CP_WAIT0();
    __syncthreads();

    // BN + ReLU in registers
    #pragma unroll
    for (int mt = 0; mt < 4; mt++) {
        int ob = wm * 64 + mt * 16 + r;
        float i0 = invS[ob],     b0 = biasS[ob];
        float i1 = invS[ob + 8], b1 = biasS[ob + 8];
        #pragma unroll
        for (int nt = 0; nt < 8; nt++) {
            cc[mt][nt][0] = fmaxf(fmaf(cc[mt][nt][0], i0, b0), 0.0f);
            cc[mt][nt][1] = fmaxf(fmaf(cc[mt][nt][1], i0, b0), 0.0f);
            cc[mt][nt][2] = fmaxf(fmaf(cc[mt][nt][2], i1, b1), 0.0f);
            cc[mt][nt][3] = fmaxf(fmaf(cc[mt][nt][3], i1, b1), 0.0f);
        }
    }

    float* S = (float*)smc;
    if (!isAtt) {
        // Stage S[o][p] (pad 260); fp16 store over p.
        #pragma unroll
        for (int mt = 0; mt < 4; mt++) {
            int ob = wm * 64 + mt * 16 + r;
            #pragma unroll
            for (int nt = 0; nt < 8; nt++) {
                int pb = wn * 64 + nt * 8 + kq * 2;
                S[ob * 260 + pb]           = cc[mt][nt][0];
                S[ob * 260 + pb + 1]       = cc[mt][nt][1];
                S[(ob + 8) * 260 + pb]     = cc[mt][nt][2];
                S[(ob + 8) * 260 + pb + 1] = cc[mt][nt][3];
            }
        }
        __syncthreads();
        #pragma unroll 4
        for (int idx = tid; idx < 8192; idx += 256) {
            int row = idx >> 6, ch = idx & 63;
            float4 v = *(const float4*)&S[row * 260 + ch * 4];
            __half2 h0 = __floats2half2_rn(v.x, v.y);
            __half2 h1 = __floats2half2_rn(v.z, v.w);
            *(uint2*)&g_feat_h[((size_t)n * COUT + br * 128 + row) * HW + p0 + ch * 4]
                = make_uint2(*(uint32_t*)&h0, *(uint32_t*)&h1);
        }
    } else {
        // Stage transposed S[p][o] (pad 132); fp16 store over c.
        #pragma unroll
        for (int mt = 0; mt < 4; mt++) {
            int ob = wm * 64 + mt * 16 + r;
            #pragma unroll
            for (int nt = 0; nt < 8; nt++) {
                int pb = wn * 64 + nt * 8 + kq * 2;
                S[pb * 132 + ob]           = cc[mt][nt][0];
                S[(pb + 1) * 132 + ob]     = cc[mt][nt][1];
                S[pb * 132 + ob + 8]       = cc[mt][nt][2];
                S[(pb + 1) * 132 + ob + 8] = cc[mt][nt][3];
            }
        }
        __syncthreads();
        #pragma unroll 4
        for (int idx = tid; idx < 8192; idx += 256) {
            int row = idx >> 5, ch = idx & 31;     // 256 p-rows x 128 c
            float4 v = *(const float4*)&S[row * 132 + ch * 4];
            __half2 h0 = __floats2half2_rn(v.x, v.y);
            __half2 h1 = __floats2half2_rn(v.z, v.w);
            *(uint2*)&g_attT_h[((size_t)n * HW + p0 + row) * CATT + ch * 4]
                = make_uint2(*(uint32_t*)&h0, *(uint32_t*)&h1);
        }
    }
}

// ===========================================================================
// Kernel 2: energy via fp16 mma (m16n8k16).
// CTA: 128(i) x 256(j), K=128 (8 k16-steps). 8 warps 2x4, warp tile 64x64.
// SMEM halves stride 136 (row = 272B = 68 words -> bank 4r+kq, conflict-free).
// ===========================================================================
#define EH_LD 136
#define E_SLD 260
#define E_SMEM 136192   // >= staging 128*260*4 = 133120 and tiles 104448

__global__ __launch_bounds__(256, 1)
void energy_mma_kernel(const float* __restrict__ mask) {
    extern __shared__ char sme[];
    __half* As = (__half*)sme;                  // 128 x EH_LD
    __half* Bs = (__half*)sme + 128 * EH_LD;    // 256 x EH_LD

    const int tid  = threadIdx.x;
    const int wid  = tid >> 5, lane = tid & 31;
    const int n  = blockIdx.z;
    const int i0 = blockIdx.y * 128;
    const int j0 = blockIdx.x * 256;
    const __half* attn = g_attT_h + (size_t)n * HW * CATT;

    #pragma unroll 4
    for (int idx = tid; idx < 2048; idx += 256) {   // A: 128 rows x 16 uint4
        int row = idx >> 4, ch = idx & 15;
        *(uint4*)&As[row * EH_LD + ch * 8] =
            *(const uint4*)(attn + (size_t)(i0 + row) * CATT + ch * 8);
    }
    #pragma unroll 4
    for (int idx = tid; idx < 4096; idx += 256) {   // B: 256 rows x 16 uint4
        int row = idx >> 4, ch = idx & 15;
        *(uint4*)&Bs[row * EH_LD + ch * 8] =
            *(const uint4*)(attn + (size_t)(j0 + row) * CATT + ch * 8);
    }
    __syncthreads();

    const int wm = wid & 1, wn = wid >> 1;
    const int r = lane >> 2, kq = lane & 3;
    float cc[4][8][4] = {};

    #pragma unroll
    for (int ks = 0; ks < 8; ks++) {
        const int k0 = ks * 16;
        uint32_t af[4][4];
        #pragma unroll
        for (int mt = 0; mt < 4; mt++) {
            int mb = wm * 64 + mt * 16;
            af[mt][0] = *(const uint32_t*)&As[(mb + r) * EH_LD + k0 + 2 * kq];
            af[mt][1] = *(const uint32_t*)&As[(mb + r + 8) * EH_LD + k0 + 2 * kq];
            af[mt][2] = *(const uint32_t*)&As[(mb + r) * EH_LD + k0 + 2 * kq + 8];
            af[mt][3] = *(const uint32_t*)&As[(mb + r + 8) * EH_LD + k0 + 2 * kq + 8];
        }
        #pragma unroll
        for (int nt = 0; nt < 8; nt++) {
            int nb = wn * 64 + nt * 8;
            uint32_t b0 = *(const uint32_t*)&Bs[(nb + r) * EH_LD + k0 + 2 * kq];
            uint32_t b1 = *(const uint32_t*)&Bs[(nb + r) * EH_LD + k0 + 2 * kq + 8];
            #pragma unroll
            for (int mt = 0; mt < 4; mt++)
                mma_f16(cc[mt][nt], af[mt][0], af[mt][1], af[mt][2], af[mt][3], b0, b1);
        }
    }
    __syncthreads();

    // Stage C f32: S[i_local][j_local], stride E_SLD; then scale+mask store.
    float* S = (float*)sme;
    #pragma unroll
    for (int mt = 0; mt < 4; mt++) {
        int ib = wm * 64 + mt * 16 + r;
        #pragma unroll
        for (int nt = 0; nt < 8; nt++) {
            int jb = wn * 64 + nt * 8 + kq * 2;
            S[ib * E_SLD + jb]           = cc[mt][nt][0];
            S[ib * E_SLD + jb + 1]       = cc[mt][nt][1];
            S[(ib + 8) * E_SLD + jb]     = cc[mt][nt][2];
            S[(ib + 8) * E_SLD + jb + 1] = cc[mt][nt][3];
        }
    }
    __syncthreads();

    const float inv_s = 0.08838834764831845f;   // 1/(1e-8+sqrt(128))
    #pragma unroll 4
    for (int idx = tid; idx < 8192; idx += 256) {
        int row = idx >> 6, ch = idx & 63;
        int j = j0 + ch * 4;
        float4 v = *(const float4*)&S[row * E_SLD + ch * 4];
        float4 mm = *(const float4*)&mask[(size_t)n * HW + j];
        v.x = v.x * inv_s + (mm.x - 1.0f) * 1e8f;
        v.y = v.y * inv_s + (mm.y - 1.0f) * 1e8f;
        v.z = v.z * inv_s + (mm.z - 1.0f) * 1e8f;
        v.w = v.w * inv_s + (mm.w - 1.0f) * 1e8f;
        *(float4*)&g_energy[((size_t)n * HW + i0 + row) * HW + j] = v;
    }
}

// ===========================================================================
// Kernel 3: row softmax — f32 in, fp16 probs out.
// ===========================================================================
__global__ void softmax_kernel() {
    const size_t row = blockIdx.x;
    const float* E = g_energy + row * HW;
    __half* P = g_prob + row * HW;
    const int tid = threadIdx.x;

    float2 v[8];
    float m = -1e30f;
    #pragma unroll
    for (int t = 0; t < 8; t++) {
        v[t] = *(const float2*)&E[t * 512 + tid * 2];
        m = fmaxf(m, fmaxf(v[t].x, v[t].y));
    }
    __shared__ float sred[8];
    #pragma unroll
    for (int o = 16; o > 0; o >>= 1)
        m = fmaxf(m, __shfl_xor_sync(0xffffffffu, m, o));
    if ((tid & 31) == 0) sred[tid >> 5] = m;
    __syncthreads();
    float mAll = sred[0];
    #pragma unroll
    for (int w = 1; w < 8; w++) mAll = fmaxf(mAll, sred[w]);

    float s = 0.0f;
    #pragma unroll
    for (int t = 0; t < 8; t++) {
        v[t].x = __expf(v[t].x - mAll);
        v[t].y = __expf(v[t].y - mAll);
        s += v[t].x + v[t].y;
    }
    #pragma unroll
    for (int o = 16; o > 0; o >>= 1)
        s += __shfl_xor_sync(0xffffffffu, s, o);
    __syncthreads();
    if ((tid & 31) == 0) sred[tid >> 5] = s;
    __syncthreads();
    float sAll = 0.0f;
    #pragma unroll
    for (int w = 0; w < 8; w++) sAll += sred[w];

    const float rr = 1.0f / sAll;
    #pragma unroll
    for (int t = 0; t < 8; t++) {
        __half2 h = __floats2half2_rn(v[t].x * rr, v[t].y * rr);
        *(__half2*)&P[t * 512 + tid * 2] = h;
    }
}

// ===========================================================================
// Kernel 4: out = prob @ feat^T via fp16 mma + cp.async 3-stage.
// CTA: M=128(i) x N=256(c), K=4096 (Kt=64 halves, 64 iters).
// SMEM halves stride 72 (row 144B -> bank 4r+kq, conflict-free).
// ===========================================================================
#define OH_LD 72
#define O_ABYTES (128 * OH_LD * 2)             // 18432
#define O_STAGE  (O_ABYTES + 256 * OH_LD * 2)  // 55296
#define O_SMEM   (3 * O_STAGE)                 // 165888
#define O_NIT    64

__global__ __launch_bounds__(256, 1)
void out_mma_kernel(const float* __restrict__ mask, float* __restrict__ out) {
    extern __shared__ char smc[];
    const uint32_t sb = smem_u32(smc);
    const int tid  = threadIdx.x;
    const int wid  = tid >> 5, lane = tid & 31;
    const int n  = blockIdx.y;
    const int i0 = blockIdx.x * 128;
    const __half* Pg = g_prob   + (size_t)n * HW * HW;   // [i][j]
    const __half* F  = g_feat_h + (size_t)n * COUT * HW; // [c][j]

    auto load_stage = [&](int s, int kt) {
        uint32_t base = sb + (uint32_t)s * O_STAGE;
        #pragma unroll
        for (int idx = tid; idx < 3072; idx += 256) {
            if (idx < 1024) {                  // A: 128 rows x 64 halves (8 CP16)
                int row = idx >> 3, ch = idx & 7;
                CP16(base + row * 144 + ch * 16,
                     Pg + (size_t)(i0 + row) * HW + kt + ch * 8);
            } else {                           // B: 256 rows x 64 halves
                int q = idx - 1024;
                int row = q >> 3, ch = q & 7;
                CP16(base + O_ABYTES + row * 144 + ch * 16,
                     F + (size_t)row * HW + kt + ch * 8);
            }
        }
        CP_COMMIT();
    };

    load_stage(0, 0);
    load_stage(1, 64);

    const int wm = wid & 1, wn = wid >> 1;
    const int r = lane >> 2, kq = lane & 3;
    float cc[4][8][4] = {};

    for (int it = 0; it < O_NIT; ++it) {
        CP_WAIT1();
        __syncthreads();
        const __half* As = (const __half*)(smc + (it % 3) * O_STAGE);
        const __half* Bs = (const __half*)(smc + (it % 3) * O_STAGE + O_ABYTES);
        #pragma unroll
        for (int ks = 0; ks < 4; ks++) {
            const int k0 = ks * 16;
            uint32_t af[4][4];
            #pragma unroll
            for (int mt = 0; mt < 4; mt++) {
                int mb = wm * 64 + mt * 16;
                af[mt][0] = *(const uint32_t*)&As[(mb + r) * OH_LD + k0 + 2 * kq];
                af[mt][1] = *(const uint32_t*)&As[(mb + r + 8) * OH_LD + k0 + 2 * kq];
                af[mt][2] = *(const uint32_t*)&As[(mb + r) * OH_LD + k0 + 2 * kq + 8];
                af[mt][3] = *(const uint32_t*)&As[(mb + r + 8) * OH_LD + k0 + 2 * kq + 8];
            }
            #pragma unroll
            for (int nt = 0; nt < 8; nt++) {
                int nb = wn * 64 + nt * 8;
                uint32_t b0 = *(const uint32_t*)&Bs[(nb + r) * OH_LD + k0 + 2 * kq];
                uint32_t b1 = *(const uint32_t*)&Bs[(nb + r) * OH_LD + k0 + 2 * kq + 8];
                #pragma unroll
                for (int mt = 0; mt < 4; mt++)
                    mma_f16(cc[mt][nt], af[mt][0], af[mt][1], af[mt][2], af[mt][3], b0, b1);
            }
        }
        __syncthreads();
        if (it + 2 < O_NIT) load_stage((it + 2) % 3, (it + 2) * 64);
        else CP_COMMIT();
    }
    CP_WAIT0();
    __syncthreads();

    // Stage C: S[c_local][i_local], stride 132; masked f32 store.
    float* S = (float*)smc;
    #pragma unroll
    for (int mt = 0; mt < 4; mt++) {
        int ib = wm * 64 + mt * 16 + r;
        #pragma unroll
        for (int nt = 0; nt < 8; nt++) {
            int cb = wn * 64 + nt * 8 + kq * 2;
            S[cb * 132 + ib]           = cc[mt][nt][0];
            S[(cb + 1) * 132 + ib]     = cc[mt][nt][1];
            S[cb * 132 + ib + 8]       = cc[mt][nt][2];
            S[(cb + 1) * 132 + ib + 8] = cc[mt][nt][3];
        }
    }
    __syncthreads();

    #pragma unroll 4
    for (int idx = tid; idx < 8192; idx += 256) {
        int row = idx >> 5, ch = idx & 31;
        int ii = i0 + ch * 4;
        float4 v = *(const float4*)&S[row * 132 + ch * 4];
        float4 mm = *(const float4*)&mask[(size_t)n * HW + ii];
        v.x *= mm.x; v.y *= mm.y; v.z *= mm.z; v.w *= mm.w;
        *(float4*)&out[((size_t)n * COUT + row) * HW + ii] = v;
    }
}

// ===========================================================================
extern "C" void kernel_launch(void* const* d_in, const int* in_sizes, int n_in,
                              void* d_out, int out_size) {
    const float* x           = (const float*)d_in[0];
    const float* mask        = (const float*)d_in[1];
    const float* reduc_w     = (const float*)d_in[2];
    const float* reduc_gamma = (const float*)d_in[3];
    const float* reduc_beta  = (const float*)d_in[4];
    const float* reduc_mean  = (const float*)d_in[5];
    const float* reduc_var   = (const float*)d_in[6];
    const float* att_w       = (const float*)d_in[7];
    const float* att_gamma   = (const float*)d_in[8];
    const float* att_beta    = (const float*)d_in[9];
    const float* att_mean    = (const float*)d_in[10];
    const float* att_var     = (const float*)d_in[11];
    float* out = (float*)d_out;

    cudaFuncSetAttribute(conv_mma_kernel,   cudaFuncAttributeMaxDynamicSharedMemorySize, C_SMEM);
    cudaFuncSetAttribute(energy_mma_kernel, cudaFuncAttributeMaxDynamicSharedMemorySize, E_SMEM);
    cudaFuncSetAttribute(out_mma_kernel,    cudaFuncAttributeMaxDynamicSharedMemorySize, O_SMEM);

    prep_kernel<<<8192, 256>>>(x, reduc_w, att_w);

    conv_mma_kernel<<<dim3(HW / 256, 3, NB), 256, C_SMEM>>>(
        reduc_gamma, reduc_beta, reduc_mean, reduc_var,
        att_gamma, att_beta, att_mean, att_var);

    energy_mma_kernel<<<dim3(HW / 256, HW / 128, NB), 256, E_SMEM>>>(mask);

    softmax_kernel<<<NB * HW, 256>>>();

    out_mma_kernel<<<dim3(HW / 128, NB), 256, O_SMEM>>>(mask, out);
}